// round 11
// baseline (speedup 1.0000x reference)
#include <cuda_runtime.h>
#include <cuda_fp16.h>

#define T_STEPS 1024
#define BATCH   64
#define ICH     512
#define HCH     512
#define G4      2048
#define NBLK    128
#define NTHR    512

// ---------------- scratch (static device globals; no allocation) ------------
__device__ __align__(16) float  g_xi[134217728];       // [T][B][2048] layer0 xi (512MB)
__device__ __align__(16) __half g_x16[33554432];       // x converted to fp16 (64MB)
__device__ __align__(16) __half g_h0[4][BATCH*HCH];    // layer0 h ring (fragment-packed)
__device__ __align__(16) __half g_h1[4][BATCH*HCH];    // layer1 h ring
__device__ __align__(16) uint4  g_wf0[NBLK*1024];      // layer0 Wh fragment-major
__device__ __align__(16) uint4  g_wf1[NBLK*2*1024];    // layer1 {Wi,Wh} fragment-major
__device__ __align__(16) uint4  g_wfi0[NBLK*1024];     // layer0 Wi fragment-major (GEMM B)
__device__ __align__(16) float  g_bias_r[2*G4];        // bi+bh, interleaved, both layers
__device__ int g_cnt;

// ---------------- helpers ---------------------------------------------------
__device__ __forceinline__ void mma_f16(float acc[4],
                                        unsigned a0, unsigned a1, unsigned a2, unsigned a3,
                                        unsigned b0, unsigned b1) {
    asm volatile(
        "mma.sync.aligned.m16n8k16.row.col.f32.f16.f16.f32 "
        "{%0,%1,%2,%3},{%4,%5,%6,%7},{%8,%9},{%0,%1,%2,%3};"
        : "+f"(acc[0]), "+f"(acc[1]), "+f"(acc[2]), "+f"(acc[3])
        : "r"(a0), "r"(a1), "r"(a2), "r"(a3), "r"(b0), "r"(b1));
}
__device__ __forceinline__ float sigmf(float x) {
    return __fdividef(1.f, 1.f + __expf(-x));
}
__device__ __forceinline__ float tanhfast(float x) {
    float e = __expf(2.f * x);
    return 1.f - __fdividef(2.f, e + 1.f);
}
__device__ __forceinline__ int ld_relaxed(const int* p) {
    int v;
    asm volatile("ld.relaxed.gpu.global.b32 %0, [%1];" : "=r"(v) : "l"(p) : "memory");
    return v;
}
__device__ __forceinline__ void red_add_relaxed(int* p, int v) {
    asm volatile("red.relaxed.gpu.global.add.s32 [%0], %1;" :: "l"(p), "r"(v) : "memory");
}
__device__ __forceinline__ void fence_gpu() {
    asm volatile("fence.acq_rel.gpu;" ::: "memory");
}
__device__ __forceinline__ uint4 ldcg4(const uint4* p) { return __ldcg(p); }

// ---------------- init: reset counter (per graph replay) --------------------
__global__ void k_init() { g_cnt = 0; }

// ---------------- x -> fp16 -------------------------------------------------
__global__ void k_x16(const float* __restrict__ x) {
    size_t i = (size_t)blockIdx.x * 256 + threadIdx.x;   // over 4194304 (8 halves each)
    const float4* src = (const float4*)x + i * 2;
    float4 v0 = src[0], v1 = src[1];
    __half2 h0 = __floats2half2_rn(v0.x, v0.y);
    __half2 h1 = __floats2half2_rn(v0.z, v0.w);
    __half2 h2 = __floats2half2_rn(v1.x, v1.y);
    __half2 h3 = __floats2half2_rn(v1.z, v1.w);
    uint4 o;
    o.x = *(unsigned*)&h0; o.y = *(unsigned*)&h1;
    o.z = *(unsigned*)&h2; o.w = *(unsigned*)&h3;
    *((uint4*)g_x16 + i) = o;
}

// ---------------- bias (bi+bh), interleaved, both layers --------------------
__global__ void k_bias(const float* __restrict__ bi, const float* __restrict__ bh) {
    int idx = blockIdx.x * 1024 + threadIdx.x;   // over 2*2048
    int l = idx >> 11, np = idx & 2047;
    int s = np & 3, j = np >> 2;
    g_bias_r[idx] = bi[l * G4 + s * 512 + j] + bh[l * G4 + s * 512 + j];
}

// ---------------- weight fragment tables ------------------------------------
// Fragment uint (2 halves): group G, m 0..31, lane (gr=lane>>2, q=lane&3),
// uw: nt = uw>>1, jp = uw&1.  Interleaved gate row = 16G + nt*8 + gr
// (raw row s*512+j with s=row&3, j=row>>2), k = 16m + 4q + 2jp + {0,1}.
// Segments: [0,524288) layer0 Wh -> g_wf0; [524288,1572864) layer1 {Wi,Wh}
// -> g_wf1; [1572864,2097152) layer0 Wi -> g_wfi0 (GEMM B operand).
__global__ void k_wfrag(const float* __restrict__ Wi, const float* __restrict__ Wh) {
    unsigned idx = blockIdx.x * 256u + threadIdx.x;
    if (idx >= 2097152u) return;
    unsigned fi, G, m, lane, uw;
    const float* src;
    unsigned* dst;
    if (idx < 524288u) {
        fi = idx; dst = (unsigned*)g_wf0;
        G = fi >> 12; m = (fi >> 7) & 31; lane = (fi >> 2) & 31; uw = fi & 3;
        src = Wh;
    } else if (idx < 1572864u) {
        fi = idx - 524288u; dst = (unsigned*)g_wf1;
        G = fi >> 13;
        unsigned kc = (fi >> 12) & 1;
        m = (fi >> 7) & 31; lane = (fi >> 2) & 31; uw = fi & 3;
        src = (kc == 0) ? (Wi + (size_t)G4 * ICH) : (Wh + (size_t)G4 * HCH);
    } else {
        fi = idx - 1572864u; dst = (unsigned*)g_wfi0;
        G = fi >> 12; m = (fi >> 7) & 31; lane = (fi >> 2) & 31; uw = fi & 3;
        src = Wi;
    }
    int nt = uw >> 1, jp = uw & 1;
    int gr = lane >> 2, q = lane & 3;
    int rowp = 16 * G + nt * 8 + gr;
    int s = rowp & 3, jr = rowp >> 2;
    int k = 16 * m + 4 * q + 2 * jp;
    const float* p = src + (size_t)(s * 512 + jr) * 512 + k;
    __half2 h = __floats2half2_rn(p[0], p[1]);
    dst[fi] = *(unsigned*)&h;
}

// ---------------- layer0 input-projection GEMM ------------------------------
// C[65536, 2048] = x16[65536, 512] x Wi0[2048, 512]^T + bias0
// A staged fp16 in smem (uint2 fragment loads, table k-permutation);
// B read directly from g_wfi0 fragment table via __ldg (no smem).
__global__ __launch_bounds__(256) void k_gemm() {
    __shared__ unsigned As[128][20];

    int n0 = blockIdx.x * 64, m0 = blockIdx.y * 128;
    int tid = threadIdx.x, lane = tid & 31, warp = tid >> 5;
    int q = lane & 3, gr = lane >> 2;
    int wm = warp & 3, wn = warp >> 2;
    int Gb = (n0 >> 4) + wn * 2;

    float acc[2][4][4];
#pragma unroll
    for (int mi = 0; mi < 2; mi++)
#pragma unroll
        for (int ni = 0; ni < 4; ni++)
#pragma unroll
            for (int e = 0; e < 4; e++) acc[mi][ni][e] = 0.f;

    for (int k0 = 0; k0 < 512; k0 += 32) {
        // stage A tile: 128 rows x 32 halves (512 uint4, 2 per thread)
#pragma unroll
        for (int i = 0; i < 2; i++) {
            int f = tid + i * 256;
            int r = f >> 2, seg = f & 3;
            uint4 v = *(const uint4*)&g_x16[(size_t)(m0 + r) * 512 + k0 + seg * 8];
            *(uint4*)&As[r][seg * 4] = v;
        }
        __syncthreads();

#pragma unroll
        for (int kt = 0; kt < 2; kt++) {
            int m = (k0 >> 4) + kt;
            uint4 w0 = __ldg(&g_wfi0[(size_t)Gb * 1024 + m * 32 + lane]);
            uint4 w1 = __ldg(&g_wfi0[(size_t)(Gb + 1) * 1024 + m * 32 + lane]);
            unsigned a[2][4];
#pragma unroll
            for (int mi = 0; mi < 2; mi++) {
                int r0 = wm * 32 + mi * 16 + gr;
                uint2 ua = *(uint2*)&As[r0][kt * 8 + 2 * q];
                uint2 ub = *(uint2*)&As[r0 + 8][kt * 8 + 2 * q];
                a[mi][0] = ua.x; a[mi][1] = ub.x; a[mi][2] = ua.y; a[mi][3] = ub.y;
            }
#pragma unroll
            for (int mi = 0; mi < 2; mi++) {
                mma_f16(acc[mi][0], a[mi][0], a[mi][1], a[mi][2], a[mi][3], w0.x, w0.y);
                mma_f16(acc[mi][1], a[mi][0], a[mi][1], a[mi][2], a[mi][3], w0.z, w0.w);
                mma_f16(acc[mi][2], a[mi][0], a[mi][1], a[mi][2], a[mi][3], w1.x, w1.y);
                mma_f16(acc[mi][3], a[mi][0], a[mi][1], a[mi][2], a[mi][3], w1.z, w1.w);
            }
        }
        __syncthreads();
    }

    // epilogue: ni -> gate row n0 + wn*32 + (ni>>1)*16 + (ni&1)*8 + gr, col +2q
#pragma unroll
    for (int mi = 0; mi < 2; mi++)
#pragma unroll
        for (int ni = 0; ni < 4; ni++) {
            int row  = m0 + wm * 32 + mi * 16 + gr;
            int ncol = n0 + wn * 32 + (ni >> 1) * 16 + (ni & 1) * 8 + 2 * q;
            float2 bb = *(const float2*)&g_bias_r[ncol];
            float2 o;
            o.x = acc[mi][ni][0] + bb.x; o.y = acc[mi][ni][1] + bb.y;
            *(float2*)&g_xi[(size_t)row * G4 + ncol] = o;
            o.x = acc[mi][ni][2] + bb.x; o.y = acc[mi][ni][3] + bb.y;
            *(float2*)&g_xi[(size_t)(row + 8) * G4 + ncol] = o;
        }
}

// ---------------- fused 2-layer persistent recurrent kernel -----------------
// 128 blocks x 512 threads (16 warps). Block b owns, for BOTH layers, gate'
// rows [16b,16b+16) <-> h cols [4b,4b+4).  Warp = (chunk = batch-group 0..3,
// kq = K-quarter 0..3).  Round r: L0 step r (K=512, warp does 8 m16-chunks)
// and L1 step r-2 (K=1024, warp does 16 m; kq<2 -> Wi1*h0, kq>=2 -> Wh1*h1).
// 8 partial-gate buffers summed in the cell. 4-deep h rings license the lag.
__global__ __launch_bounds__(NTHR, 1) void k_fused(const float* __restrict__ h0in,
                                                   const float* __restrict__ c0in,
                                                   float* __restrict__ y,
                                                   float* __restrict__ hT,
                                                   float* __restrict__ cT) {
    __shared__ float sGp[8][64][20];   // [0..3]=L0 by kq, [4..7]=L1 by kq

    int b = blockIdx.x, tid = threadIdx.x;
    int lane = tid & 31, w = tid >> 5;
    int q = lane & 3, gr = lane >> 2;
    int chunk = w & 3, kq = w >> 2;

    int batch = tid >> 2, jl = tid & 3;      // cell mapping (tid<256 only)
    int col = 4 * b + jl;

    // publish address (half granularity) in the fragment-packed h rings
    int u4i = (batch >> 4) * 1024 + (b >> 2) * 32 + ((batch & 7) << 2) + (b & 3);
    int haddr = u4i * 8 + ((batch >> 3) & 1) * 4 + jl;

    // init c and h_0 for both layers (cell threads only), publish (arrival #1)
    float creg0 = 0.f, creg1 = 0.f;
    if (tid < 256) {
        creg0 = c0in[batch * HCH + col];
        creg1 = c0in[BATCH * HCH + batch * HCH + col];
        ((__half*)g_h0[0])[haddr] = __float2half_rn(h0in[batch * HCH + col]);
        ((__half*)g_h1[0])[haddr] = __float2half_rn(h0in[BATCH * HCH + batch * HCH + col]);
    }
    __syncthreads();
    if (tid == 0) { fence_gpu(); red_add_relaxed(&g_cnt, 1); }

    float4 bb = *(const float4*)&g_bias_r[G4 + 16 * b + 4 * jl];   // layer1 bias

    const uint4* wA = g_wf0 + b * 1024;                 // + m*32 + lane
    const int kc     = kq >> 1;                         // L1 source selector
    const uint4* wB  = g_wf1 + (b * 2 + kc) * 1024;
    const int mB0    = (kq & 1) * 16;                   // L1 m base within source
    const int mA0    = kq * 8;                          // L0 m base
    const int loff   = chunk * 1024 + lane;

    for (int r = 0; r < 1026; ++r) {
        // prefetch xi_r before the wait
        float4 xv = make_float4(0.f, 0.f, 0.f, 0.f);
        if (r < T_STEPS && tid < 256)
            xv = __ldcg((const float4*)&g_xi[(size_t)r * BATCH * G4 + batch * G4 + 16 * b + 4 * jl]);

        // wait: all round r-1 publications visible
        if (tid == 0) {
            int need = (r + 1) * NBLK;
            while (ld_relaxed(&g_cnt) < need) {}
            fence_gpu();
        }
        __syncthreads();

        // ---- phase A: layer0 step r (8 m, 16 mma) ----
        if (r < T_STEPS) {
            const uint4* hA = (const uint4*)g_h0[r & 3] + loff;
            float acc[2][4] = {{0.f,0.f,0.f,0.f},{0.f,0.f,0.f,0.f}};
            uint4 hr[8], wr[8];
#pragma unroll
            for (int u = 0; u < 8; u++) {
                int m = mA0 + u;
                hr[u] = ldcg4(hA + m * 32);
                wr[u] = __ldg(wA + m * 32 + lane);
            }
#pragma unroll
            for (int u = 0; u < 8; u++) {
                mma_f16(acc[0], hr[u].x, hr[u].z, hr[u].y, hr[u].w, wr[u].x, wr[u].y);
                mma_f16(acc[1], hr[u].x, hr[u].z, hr[u].y, hr[u].w, wr[u].z, wr[u].w);
            }
#pragma unroll
            for (int nt = 0; nt < 2; nt++) {
                *(float2*)&sGp[kq][16 * chunk + gr][nt * 8 + 2 * q] =
                    make_float2(acc[nt][0], acc[nt][1]);
                *(float2*)&sGp[kq][16 * chunk + gr + 8][nt * 8 + 2 * q] =
                    make_float2(acc[nt][2], acc[nt][3]);
            }
        }

        // ---- phase B: layer1 step r-2 (16 m, 32 mma; 2-stage pipeline) ----
        if (r >= 2) {
            const uint4* hB = (kc == 0)
                ? (const uint4*)g_h0[(r - 1) & 3] + loff     // x-input = L0 step r-2 out
                : (const uint4*)g_h1[(r - 2) & 3] + loff;    // recurrent = L1 step r-3 out
            float acc[2][4] = {{0.f,0.f,0.f,0.f},{0.f,0.f,0.f,0.f}};
            uint4 hr[2][8], wr[2][8];
#pragma unroll
            for (int u = 0; u < 8; u++) {
                int m = mB0 + u;
                hr[0][u] = ldcg4(hB + m * 32);
                wr[0][u] = __ldg(wB + m * 32 + lane);
            }
#pragma unroll
            for (int st = 0; st < 2; st++) {
                if (st == 0) {
#pragma unroll
                    for (int u = 0; u < 8; u++) {
                        int m = mB0 + 8 + u;
                        hr[1][u] = ldcg4(hB + m * 32);
                        wr[1][u] = __ldg(wB + m * 32 + lane);
                    }
                }
#pragma unroll
                for (int u = 0; u < 8; u++) {
                    mma_f16(acc[0], hr[st][u].x, hr[st][u].z, hr[st][u].y, hr[st][u].w,
                            wr[st][u].x, wr[st][u].y);
                    mma_f16(acc[1], hr[st][u].x, hr[st][u].z, hr[st][u].y, hr[st][u].w,
                            wr[st][u].z, wr[st][u].w);
                }
            }
#pragma unroll
            for (int nt = 0; nt < 2; nt++) {
                *(float2*)&sGp[4 + kq][16 * chunk + gr][nt * 8 + 2 * q] =
                    make_float2(acc[nt][0], acc[nt][1]);
                *(float2*)&sGp[4 + kq][16 * chunk + gr + 8][nt * 8 + 2 * q] =
                    make_float2(acc[nt][2], acc[nt][3]);
            }
        }
        __syncthreads();

        // ---- cells (tid<256): sum 4 K-split partials, update, publish ----
        float hv1 = 0.f;
        if (tid < 256) {
            if (r < T_STEPS) {
                float4 p0 = *(const float4*)&sGp[0][batch][4 * jl];
                float4 p1 = *(const float4*)&sGp[1][batch][4 * jl];
                float4 p2 = *(const float4*)&sGp[2][batch][4 * jl];
                float4 p3 = *(const float4*)&sGp[3][batch][4 * jl];
                float s0 = p0.x + p1.x + p2.x + p3.x + xv.x;
                float s1 = p0.y + p1.y + p2.y + p3.y + xv.y;
                float s2 = p0.z + p1.z + p2.z + p3.z + xv.z;
                float s3 = p0.w + p1.w + p2.w + p3.w + xv.w;
                float f  = sigmf(s0), ii = sigmf(s1), o = sigmf(s2), g = tanhfast(s3);
                float c  = creg0 * f + ii * g;
                creg0 = c;
                float hv0 = o * tanhfast(c);
                ((__half*)g_h0[(r + 1) & 3])[haddr] = __float2half_rn(hv0);
                if (r == T_STEPS - 1) {
                    hT[batch * HCH + col] = hv0;
                    cT[batch * HCH + col] = creg0;
                }
            }
            if (r >= 2) {
                float4 p0 = *(const float4*)&sGp[4][batch][4 * jl];
                float4 p1 = *(const float4*)&sGp[5][batch][4 * jl];
                float4 p2 = *(const float4*)&sGp[6][batch][4 * jl];
                float4 p3 = *(const float4*)&sGp[7][batch][4 * jl];
                float s0 = p0.x + p1.x + p2.x + p3.x + bb.x;
                float s1 = p0.y + p1.y + p2.y + p3.y + bb.y;
                float s2 = p0.z + p1.z + p2.z + p3.z + bb.z;
                float s3 = p0.w + p1.w + p2.w + p3.w + bb.w;
                float f  = sigmf(s0), ii = sigmf(s1), o = sigmf(s2), g = tanhfast(s3);
                float c  = creg1 * f + ii * g;
                creg1 = c;
                hv1 = o * tanhfast(c);
                ((__half*)g_h1[(r - 1) & 3])[haddr] = __float2half_rn(hv1);
            }
        }
        __syncthreads();
        if (tid == 0 && r < 1025) { fence_gpu(); red_add_relaxed(&g_cnt, 1); }

        // ---- off-critical-path outputs ----
        if (tid < 256 && r >= 2) {
            y[(size_t)(r - 2) * BATCH * HCH + batch * HCH + col] = hv1;
            if (r == 1025) {
                hT[BATCH * HCH + batch * HCH + col] = hv1;
                cT[BATCH * HCH + batch * HCH + col] = creg1;
            }
        }
    }
}

// ---------------- launch ----------------------------------------------------
extern "C" void kernel_launch(void* const* d_in, const int* in_sizes, int n_in,
                              void* d_out, int out_size) {
    const float* x  = (const float*)d_in[0];
    const float* Wi = (const float*)d_in[1];
    const float* bi = (const float*)d_in[2];
    const float* Wh = (const float*)d_in[3];
    const float* bh = (const float*)d_in[4];
    const float* h0 = (const float*)d_in[5];
    const float* c0 = (const float*)d_in[6];

    float* out = (float*)d_out;
    float* y   = out;                                   // [T,B,HC]
    float* hsO = out + (size_t)T_STEPS * BATCH * HCH;   // [L,B,HC]
    float* csO = hsO + (size_t)2 * BATCH * HCH;         // [L,B,HC]

    k_x16<<<16384, 256>>>(x);
    k_bias<<<4, 1024>>>(bi, bh);
    k_wfrag<<<8192, 256>>>(Wi, Wh);
    k_gemm<<<dim3(32, 512), 256>>>();
    k_init<<<1, 1>>>();
    k_fused<<<NBLK, NTHR>>>(h0, c0, y, hsO, csO);

    (void)in_sizes; (void)n_in; (void)out_size;
}